// round 11
// baseline (speedup 1.0000x reference)
#include <cuda_runtime.h>

#define NUM_GRAPHS   4096
#define NUM_ELEMENTS 120
#define EMB_DIM      64
#define HID_DIM      64

__device__ float g_table[NUM_ELEMENTS];

// ---------------------------------------------------------------------------
// Node P (critical path prefix): build the 120-entry table
//   table[e] = silu(emb[e] @ W1 + b1) @ W2 + b2
// (per-atom energy depends only on z, so the MLP collapses to this LUT)
// and zero the energy[4096]/counts[4096] accumulator regions (~32 KB).
// ---------------------------------------------------------------------------
__global__ void __launch_bounds__(128)
prep_kernel(const float* __restrict__ emb,
            const float* __restrict__ W1,
            const float* __restrict__ b1,
            const float* __restrict__ W2,
            const float* __restrict__ b2,
            float4* __restrict__ energy4,   // 1024 float4
            float4* __restrict__ counts4)   // 1024 float4
{
    if (blockIdx.x < NUM_ELEMENTS) {
        __shared__ float partial[2];
        int e = blockIdx.x;
        int j = threadIdx.x;
        if (j < HID_DIM) {
            float acc = 0.0f;
#pragma unroll
            for (int k = 0; k < EMB_DIM; ++k)
                acc = fmaf(emb[e * EMB_DIM + k], W1[k * HID_DIM + j], acc);
            acc += b1[j];
            float s = acc / (1.0f + expf(-acc));   // silu
            float v = s * W2[j];
#pragma unroll
            for (int o = 16; o > 0; o >>= 1)
                v += __shfl_down_sync(0xffffffffu, v, o);
            if ((j & 31) == 0) partial[j >> 5] = v;
        }
        __syncthreads();
        if (threadIdx.x == 0) g_table[e] = partial[0] + partial[1] + b2[0];
    }

    int t = blockIdx.x * blockDim.x + threadIdx.x;
    int stride = gridDim.x * blockDim.x;
    float4 zf = make_float4(0.f, 0.f, 0.f, 0.f);
    for (int i = t; i < NUM_GRAPHS / 4; i += stride) {
        energy4[i] = zf;
        counts4[i] = zf;
    }
}

// ---------------------------------------------------------------------------
// Node Z (side branch, fully overlapped): zero the 12 MB forces region.
// forces = -grad_pos = exactly 0: the reference energy never reads pos.
// ---------------------------------------------------------------------------
__global__ void __launch_bounds__(256)
zero_forces_kernel(float4* __restrict__ forces4, int nf4) {
    int t = blockIdx.x * 256 + threadIdx.x;
    int stride = gridDim.x * 256;
    float4 zf = make_float4(0.f, 0.f, 0.f, 0.f);
    for (int i = t; i < nf4; i += stride)
        forces4[i] = zf;
}

// ---------------------------------------------------------------------------
// Node R: pure streaming segmented reduction, 4 atoms/thread (no fill work
// on the critical path anymore). batch sorted => a warp's 128 contiguous
// atoms belong to one graph iff first/last batch values match. Fast path
// (~87% of warps): count = 4*popc(active), sum via 5-shuffle butterfly.
// Boundary warps: segmented shuffle scan. ~36K atomic pairs over 4096 addrs.
// ---------------------------------------------------------------------------
__global__ void __launch_bounds__(256)
reduce_kernel(const int4* __restrict__ z4,
              const int4* __restrict__ b4,
              float* __restrict__ energy,     // out[0..4096)
              float* __restrict__ counts,     // out[4096+3N..)
              int n4)                         // n_atoms/4
{
    __shared__ float s_table[NUM_ELEMENTS];

    const unsigned FULL = 0xffffffffu;
    int t    = blockIdx.x * 256 + threadIdx.x;
    int lane = threadIdx.x & 31;

    // issue the big loads first
    bool act = (t < n4);
    int4 zz = act ? z4[t] : make_int4(0, 0, 0, 0);
    int4 bb = act ? b4[t] : make_int4(-1, -1, -1, -1);

    // stage table in the load shadow
    for (int i = threadIdx.x; i < NUM_ELEMENTS; i += 256)
        s_table[i] = g_table[i];
    __syncthreads();

    unsigned actmask = __ballot_sync(FULL, act);
    if (actmask == 0u) return;

    int nact   = __popc(actmask);
    int hi_act = 31 - __clz(actmask);
    int gfirst = __shfl_sync(FULL, bb.x, 0);
    int glast  = __shfl_sync(FULL, bb.w, hi_act);

    if (gfirst == glast && gfirst >= 0) {
        // whole warp one graph: no transitions anywhere
        float s = act ? (s_table[zz.x] + s_table[zz.y] +
                         s_table[zz.z] + s_table[zz.w]) : 0.f;
#pragma unroll
        for (int o = 16; o > 0; o >>= 1)
            s += __shfl_xor_sync(FULL, s, o);
        if (lane == 0) {
            atomicAdd(&energy[gfirst], s);
            atomicAdd(&counts[gfirst], 4.f * (float)nact);
        }
        return;
    }

    // boundary warp: per-thread run accumulation over 4 atoms
    int   runG   = -1;
    float runSum = 0.f;
    float runCnt = 0.f;
    if (act) {
        runG = bb.x; runSum = s_table[zz.x]; runCnt = 1.f;
        int gs[3] = { bb.y, bb.z, bb.w };
        int zs[3] = { zz.y, zz.z, zz.w };
#pragma unroll
        for (int k = 0; k < 3; ++k) {
            if (gs[k] == runG) { runSum += s_table[zs[k]]; runCnt += 1.f; }
            else {
                atomicAdd(&energy[runG], runSum);
                atomicAdd(&counts[runG], runCnt);
                runG = gs[k]; runSum = s_table[zs[k]]; runCnt = 1.f;
            }
        }
    }

    // segmented inclusive scan keyed by runG (non-decreasing over lanes)
#pragma unroll
    for (int d = 1; d < 32; d <<= 1) {
        float su = __shfl_up_sync(FULL, runSum, d);
        float cu = __shfl_up_sync(FULL, runCnt, d);
        int   gu = __shfl_up_sync(FULL, runG,   d);
        if (lane >= d && gu == runG) { runSum += su; runCnt += cu; }
    }
    int gnext = __shfl_down_sync(FULL, runG, 1);
    bool lastOfSeg = (lane == 31) || (gnext != runG);
    if (lastOfSeg && runG >= 0 && runG < NUM_GRAPHS) {
        atomicAdd(&energy[runG], runSum);
        atomicAdd(&counts[runG], runCnt);
    }
}

// ---------------------------------------------------------------------------
// kernel_launch — graph topology:
//   stream0: prep ──────────────> reduce ──┐ (waits evJoin)
//   s2:      (waits evFork) zero_forces ───┘
// inputs per metadata order:
//   0: z (int32, N)   1: pos (f32, 3N)  2: batch (int32, N)
//   3: emb (f32)      4: W1 (f32)       5: b1 (f32)
//   6: W2 (f32)       7: b2 (f32)
// out: f32 [energy 4096 | forces 3N | num_atoms 4096]
// ---------------------------------------------------------------------------
extern "C" void kernel_launch(void* const* d_in, const int* in_sizes, int n_in,
                              void* d_out, int out_size) {
    const int*   z     = (const int*)  d_in[0];
    const int*   batch = (const int*)  d_in[2];
    const float* emb   = (const float*)d_in[3];
    const float* W1    = (const float*)d_in[4];
    const float* b1    = (const float*)d_in[5];
    const float* W2    = (const float*)d_in[6];
    const float* b2    = (const float*)d_in[7];
    float*       out   = (float*)d_out;
    int n_atoms = in_sizes[0];

    float* energy = out;
    float* forces = out + NUM_GRAPHS;
    float* counts = out + NUM_GRAPHS + 3LL * n_atoms;

    int n4  = n_atoms >> 2;          // 250000 (n_atoms % 4 == 0 here)
    int nf4 = (3 * n_atoms) >> 2;    // 750000

    // Created once, on the first (non-capture, correctness) call; replays
    // and the capture call reuse them. No per-call resource churn.
    static cudaStream_t s2 = 0;
    static cudaEvent_t  evFork = 0, evJoin = 0;
    if (s2 == 0) {
        cudaStreamCreateWithFlags(&s2, cudaStreamNonBlocking);
        cudaEventCreateWithFlags(&evFork, cudaEventDisableTiming);
        cudaEventCreateWithFlags(&evJoin, cudaEventDisableTiming);
    }

    // fork: side branch zeros forces while the critical path runs prep+reduce
    cudaEventRecord(evFork, 0);
    cudaStreamWaitEvent(s2, evFork, 0);
    zero_forces_kernel<<<1184, 256, 0, s2>>>((float4*)forces, nf4);
    cudaEventRecord(evJoin, s2);

    // critical path
    prep_kernel<<<152, 128>>>(emb, W1, b1, W2, b2,
                              (float4*)energy, (float4*)counts);
    reduce_kernel<<<977, 256>>>((const int4*)z, (const int4*)batch,
                                energy, counts, n4);

    // join: graph end waits for the side branch
    cudaStreamWaitEvent(0, evJoin, 0);
}

// round 12
// speedup vs baseline: 1.1994x; 1.1994x over previous
#include <cuda_runtime.h>

#define NUM_GRAPHS   4096
#define NUM_ELEMENTS 120
#define EMB_DIM      64
#define HID_DIM      64

__device__ float g_table[NUM_ELEMENTS];

// ---------------------------------------------------------------------------
// Kernel A: build the 120-entry table
//   table[e] = silu(emb[e] @ W1 + b1) @ W2 + b2
// (per-atom energy depends only on z, so the MLP collapses to this LUT)
// and zero the energy[4096]/counts[4096] accumulator regions (~32 KB).
// Ends with a PDL trigger so the dependent scan kernel can launch early.
// ---------------------------------------------------------------------------
__global__ void __launch_bounds__(128)
prep_kernel(const float* __restrict__ emb,
            const float* __restrict__ W1,
            const float* __restrict__ b1,
            const float* __restrict__ W2,
            const float* __restrict__ b2,
            float4* __restrict__ energy4,   // 1024 float4
            float4* __restrict__ counts4)   // 1024 float4
{
    if (blockIdx.x < NUM_ELEMENTS) {
        __shared__ float partial[2];
        int e = blockIdx.x;
        int j = threadIdx.x;
        if (j < HID_DIM) {
            float acc = 0.0f;
#pragma unroll
            for (int k = 0; k < EMB_DIM; ++k)
                acc = fmaf(emb[e * EMB_DIM + k], W1[k * HID_DIM + j], acc);
            acc += b1[j];
            float s = acc / (1.0f + expf(-acc));   // silu
            float v = s * W2[j];
#pragma unroll
            for (int o = 16; o > 0; o >>= 1)
                v += __shfl_down_sync(0xffffffffu, v, o);
            if ((j & 31) == 0) partial[j >> 5] = v;
        }
        __syncthreads();
        if (threadIdx.x == 0) g_table[e] = partial[0] + partial[1] + b2[0];
    }

    int t = blockIdx.x * blockDim.x + threadIdx.x;
    int stride = gridDim.x * blockDim.x;
    float4 zf = make_float4(0.f, 0.f, 0.f, 0.f);
    for (int i = t; i < NUM_GRAPHS / 4; i += stride) {
        energy4[i] = zf;
        counts4[i] = zf;
    }

#if __CUDA_ARCH__ >= 900
    cudaTriggerProgrammaticLaunchCompletion();
#endif
}

// ---------------------------------------------------------------------------
// Kernel B (PDL dependent): launches while prep is still running. Phase 1
// (prep-independent): issue z/batch loads, zero the 12 MB forces region
// (forces = -grad_pos = exactly 0: energy never reads pos). Then
// cudaGridDependencySynchronize() guarantees prep's table + zeroed
// accumulators are visible; phase 2 consumes. batch sorted => warp-uniform
// fast path (~87% of warps): count = 4*popc(active), sum via 5-shuffle
// butterfly; boundary warps use a segmented shuffle scan.
// ---------------------------------------------------------------------------
__global__ void __launch_bounds__(256)
scan_kernel(const int4* __restrict__ z4,
            const int4* __restrict__ b4,
            float4* __restrict__ forces4,   // out+4096 as float4
            int nf4,                        // 3*n_atoms/4
            float* __restrict__ energy,     // out[0..4096)
            float* __restrict__ counts,     // out[4096+3N..)
            int n4)                         // n_atoms/4
{
    __shared__ float s_table[NUM_ELEMENTS];

    const unsigned FULL = 0xffffffffu;
    int t    = blockIdx.x * 256 + threadIdx.x;
    int lane = threadIdx.x & 31;

    // ---- phase 1: prep-independent work ----
    bool act = (t < n4);
    int4 zz = act ? z4[t] : make_int4(0, 0, 0, 0);
    int4 bb = act ? b4[t] : make_int4(-1, -1, -1, -1);

    {
        float4 zf = make_float4(0.f, 0.f, 0.f, 0.f);
        int stride = gridDim.x * 256;
        for (int i = t; i < nf4; i += stride)
            forces4[i] = zf;
    }

    // ---- wait for prep's memory (table + zeroed accumulators) ----
#if __CUDA_ARCH__ >= 900
    cudaGridDependencySynchronize();
#endif

    for (int i = threadIdx.x; i < NUM_ELEMENTS; i += 256)
        s_table[i] = g_table[i];
    __syncthreads();

    unsigned actmask = __ballot_sync(FULL, act);
    if (actmask == 0u) return;

    int nact   = __popc(actmask);
    int hi_act = 31 - __clz(actmask);
    int gfirst = __shfl_sync(FULL, bb.x, 0);
    int glast  = __shfl_sync(FULL, bb.w, hi_act);

    if (gfirst == glast && gfirst >= 0) {
        // whole warp one graph: no transitions anywhere
        float s = act ? (s_table[zz.x] + s_table[zz.y] +
                         s_table[zz.z] + s_table[zz.w]) : 0.f;
#pragma unroll
        for (int o = 16; o > 0; o >>= 1)
            s += __shfl_xor_sync(FULL, s, o);
        if (lane == 0) {
            atomicAdd(&energy[gfirst], s);
            atomicAdd(&counts[gfirst], 4.f * (float)nact);
        }
        return;
    }

    // boundary warp: per-thread run accumulation over 4 atoms
    int   runG   = -1;
    float runSum = 0.f;
    float runCnt = 0.f;
    if (act) {
        runG = bb.x; runSum = s_table[zz.x]; runCnt = 1.f;
        int gs[3] = { bb.y, bb.z, bb.w };
        int zs[3] = { zz.y, zz.z, zz.w };
#pragma unroll
        for (int k = 0; k < 3; ++k) {
            if (gs[k] == runG) { runSum += s_table[zs[k]]; runCnt += 1.f; }
            else {
                atomicAdd(&energy[runG], runSum);
                atomicAdd(&counts[runG], runCnt);
                runG = gs[k]; runSum = s_table[zs[k]]; runCnt = 1.f;
            }
        }
    }

    // segmented inclusive scan keyed by runG (non-decreasing over lanes)
#pragma unroll
    for (int d = 1; d < 32; d <<= 1) {
        float su = __shfl_up_sync(FULL, runSum, d);
        float cu = __shfl_up_sync(FULL, runCnt, d);
        int   gu = __shfl_up_sync(FULL, runG,   d);
        if (lane >= d && gu == runG) { runSum += su; runCnt += cu; }
    }
    int gnext = __shfl_down_sync(FULL, runG, 1);
    bool lastOfSeg = (lane == 31) || (gnext != runG);
    if (lastOfSeg && runG >= 0 && runG < NUM_GRAPHS) {
        atomicAdd(&energy[runG], runSum);
        atomicAdd(&counts[runG], runCnt);
    }
}

// ---------------------------------------------------------------------------
// kernel_launch — prep, then scan launched with Programmatic Stream
// Serialization (PDL): scan starts while prep runs; visibility enforced
// in-kernel by cudaGridDependencySynchronize().
// inputs per metadata order:
//   0: z (int32, N)   1: pos (f32, 3N)  2: batch (int32, N)
//   3: emb (f32)      4: W1 (f32)       5: b1 (f32)
//   6: W2 (f32)       7: b2 (f32)
// out: f32 [energy 4096 | forces 3N | num_atoms 4096]
// ---------------------------------------------------------------------------
extern "C" void kernel_launch(void* const* d_in, const int* in_sizes, int n_in,
                              void* d_out, int out_size) {
    const int*   z     = (const int*)  d_in[0];
    const int*   batch = (const int*)  d_in[2];
    const float* emb   = (const float*)d_in[3];
    const float* W1    = (const float*)d_in[4];
    const float* b1    = (const float*)d_in[5];
    const float* W2    = (const float*)d_in[6];
    const float* b2    = (const float*)d_in[7];
    float*       out   = (float*)d_out;
    int n_atoms = in_sizes[0];

    float* energy = out;
    float* forces = out + NUM_GRAPHS;
    float* counts = out + NUM_GRAPHS + 3LL * n_atoms;

    int n4  = n_atoms >> 2;          // 250000 (n_atoms % 4 == 0 here)
    int nf4 = (3 * n_atoms) >> 2;    // 750000

    prep_kernel<<<152, 128>>>(emb, W1, b1, W2, b2,
                              (float4*)energy, (float4*)counts);

    // scan with programmatic dependent launch
    cudaLaunchConfig_t cfg = {};
    cfg.gridDim  = dim3(1184, 1, 1);   // 8 CTAs/SM exact on 148 SMs
    cfg.blockDim = dim3(256, 1, 1);
    cfg.dynamicSmemBytes = 0;
    cfg.stream = 0;
    cudaLaunchAttribute attrs[1];
    attrs[0].id = cudaLaunchAttributeProgrammaticStreamSerialization;
    attrs[0].val.programmaticStreamSerializationAllowed = 1;
    cfg.attrs = attrs;
    cfg.numAttrs = 1;

    cudaLaunchKernelEx(&cfg, scan_kernel,
                       (const int4*)z, (const int4*)batch,
                       (float4*)forces, nf4, energy, counts, n4);
}